// round 7
// baseline (speedup 1.0000x reference)
#include <cuda_runtime.h>

// SelfNorm collapsed: out = x*std_w + mean*(mean_w - std_w), per (b,c) row.
// PERSISTENT kernel: grid = 592 CTAs (~4/SM, single wave), each CTA loops
// over rows. Double-buffered registers: next row's loads are issued before
// the current row's reduce/barrier/store, hiding DRAM latency under the
// sync bubble. Lane-parallel MLPs; weights hoisted out of the row loop.

#define HW 3136          // 56*56
#define F4 784           // HW/4 = 3*256 + 16
#define NTHREADS 256
#define NROWS 8192       // B*C
#define GRID 592         // 148 SMs * 4 CTAs, single resident wave
#define EPS 1e-5f

__device__ __forceinline__ void acc4(const float4& a, float& s, float& sq) {
    s += a.x + a.y + a.z + a.w;
    sq = fmaf(a.x, a.x, sq); sq = fmaf(a.y, a.y, sq);
    sq = fmaf(a.z, a.z, sq); sq = fmaf(a.w, a.w, sq);
}

__device__ __forceinline__ float4 xform(const float4& a, float al, float be) {
    float4 r;
    r.x = fmaf(a.x, al, be);
    r.y = fmaf(a.y, al, be);
    r.z = fmaf(a.z, al, be);
    r.w = fmaf(a.w, al, be);
    return r;
}

__global__ void __launch_bounds__(NTHREADS, 4)
selfnorm_kernel(const float4* __restrict__ x,
                const float* __restrict__ W1m, const float* __restrict__ b1m,
                const float* __restrict__ W2m, const float* __restrict__ b2m,
                const float* __restrict__ W1s, const float* __restrict__ b1s,
                const float* __restrict__ W2s, const float* __restrict__ b2s,
                float4* __restrict__ out) {
    __shared__ float ps[8], psq[8];

    const int t    = threadIdx.x;
    const int lane = t & 31;
    const int wid  = t >> 5;
    const bool rem = (t < 16);          // 784 - 3*256

    // ---- Hoisted MLP weights (lane-parallel: lane<16 mean-MLP, else std) ----
    const int  j = lane & 15;
    const bool is_m = (lane < 16);
    const float w1a = __ldg((is_m ? W1m : W1s) + 2 * j);
    const float w1b = __ldg((is_m ? W1m : W1s) + 2 * j + 1);
    const float bb1 = __ldg((is_m ? b1m : b1s) + j);
    const float w2  = __ldg((is_m ? W2m : W2s) + j);
    const float bb2 = __ldg( is_m ? b2m : b2s);

    // ---- Prologue: load first row ----
    int row = blockIdx.x;
    const float4* xr = x + (size_t)row * F4;
    float4 a0 = __ldcs(xr + t);
    float4 a1 = __ldcs(xr + t + 256);
    float4 a2 = __ldcs(xr + t + 512);
    float4 a3 = rem ? __ldcs(xr + 768 + t) : make_float4(0.f, 0.f, 0.f, 0.f);

    for (; row < NROWS; row += GRID) {
        const int nrow = row + GRID;
        const bool has_next = (nrow < NROWS);

        // ---- Stats from current registers ----
        float s = 0.0f, sq = 0.0f;
        acc4(a0, s, sq); acc4(a1, s, sq); acc4(a2, s, sq);
        if (rem) acc4(a3, s, sq);

        // ---- Prefetch next row (in flight across barrier/MLP/store) ----
        float4 b0, b1, b2, b3;
        if (has_next) {
            const float4* xn = x + (size_t)nrow * F4;
            b0 = __ldcs(xn + t);
            b1 = __ldcs(xn + t + 256);
            b2 = __ldcs(xn + t + 512);
            if (rem) b3 = __ldcs(xn + 768 + t);
        }

        // ---- Warp reduce, one barrier ----
        #pragma unroll
        for (int o = 16; o > 0; o >>= 1) {
            s  += __shfl_xor_sync(0xffffffffu, s,  o);
            sq += __shfl_xor_sync(0xffffffffu, sq, o);
        }
        if (lane == 0) { ps[wid] = s; psq[wid] = sq; }
        __syncthreads();

        float ts = 0.0f, tsq = 0.0f;
        #pragma unroll
        for (int i = 0; i < 8; i++) { ts += ps[i]; tsq += psq[i]; }
        __syncthreads();   // protect ps/psq before next iteration's writes

        const float n = (float)HW;
        const float mean = ts / n;
        float var = (tsq - n * mean * mean) / (n - 1.0f);
        var = fmaxf(var, 0.0f);
        const float std = sqrtf(var + EPS);

        // ---- Lane-parallel MLPs ----
        float h = fmaf(w1a, mean, fmaf(w1b, std, bb1));
        h = fmaxf(h, 0.0f);
        float p = w2 * h;
        #pragma unroll
        for (int o = 8; o > 0; o >>= 1)
            p += __shfl_xor_sync(0xffffffffu, p, o);
        float z = p + bb2;
        float sig = 1.0f / (1.0f + __expf(-z));

        const float mean_w = __shfl_sync(0xffffffffu, sig, 0);
        const float std_w  = __shfl_sync(0xffffffffu, sig, 16);
        const float alpha = std_w;
        const float beta  = mean * (mean_w - std_w);

        // ---- Transform + streaming store ----
        float4* orow = out + (size_t)row * F4;
        __stcs(orow + t,       xform(a0, alpha, beta));
        __stcs(orow + t + 256, xform(a1, alpha, beta));
        __stcs(orow + t + 512, xform(a2, alpha, beta));
        if (rem) __stcs(orow + 768 + t, xform(a3, alpha, beta));

        // ---- Rotate buffers ----
        if (has_next) { a0 = b0; a1 = b1; a2 = b2; if (rem) a3 = b3; }
    }
}

extern "C" void kernel_launch(void* const* d_in, const int* in_sizes, int n_in,
                              void* d_out, int out_size) {
    const float4* x  = (const float4*)d_in[0];
    const float* W1m = (const float*)d_in[1];
    const float* b1m = (const float*)d_in[2];
    const float* W2m = (const float*)d_in[3];
    const float* b2m = (const float*)d_in[4];
    const float* W1s = (const float*)d_in[5];
    const float* b1s = (const float*)d_in[6];
    const float* W2s = (const float*)d_in[7];
    const float* b2s = (const float*)d_in[8];
    float4* out = (float4*)d_out;

    selfnorm_kernel<<<GRID, NTHREADS>>>(x, W1m, b1m, W2m, b2m,
                                        W1s, b1s, W2s, b2s, out);
}